// round 1
// baseline (speedup 1.0000x reference)
#include <cuda_runtime.h>
#include <cuda_bf16.h>
#include <cstdint>

// ----------------------------------------------------------------------------
// OpenLSTM: HIDDEN=16, PROJ=2, INPUT=2. B=64, T=8192, nstep=4096.
// Phase 1 (t < nstep): gates from y_train only, fully parallel.
// Phase 2 (t >= nstep): sequential LSTM scan, one half-warp per batch.
// ----------------------------------------------------------------------------

#define HIDDEN 16
#define BATCH  64

// --- fast activations (ex2.approx + rcp.approx: ~1e-7 abs err, safe) --------
__device__ __forceinline__ float fast_ex2(float x) {
    float y;
    asm("ex2.approx.ftz.f32 %0, %1;" : "=f"(y) : "f"(x));
    return y;
}
__device__ __forceinline__ float fast_rcp(float x) {
    float y;
    asm("rcp.approx.ftz.f32 %0, %1;" : "=f"(y) : "f"(x));
    return y;
}
__device__ __forceinline__ float sigf(float x) {
    // sigmoid(x) = 1 / (1 + exp(-x)) = 1 / (1 + 2^(-x*log2e))
    return fast_rcp(1.0f + fast_ex2(-1.4426950408889634f * x));
}
__device__ __forceinline__ float tanhf_(float x) {
    // tanh(x) = 2*sigmoid(2x) - 1
    return fmaf(2.0f, sigf(2.0f * x), -1.0f);
}

// ----------------------------------------------------------------------------
// Phase 1: out[b,t,:] for t < nstep, from y_train. No recurrence (c1 = i*g).
// One thread per (b, t). Weights staged in shared memory (broadcast LDS).
// ----------------------------------------------------------------------------
__global__ void lstm_phase1(const float* __restrict__ y_train,
                            const float* __restrict__ W_ih,
                            const float* __restrict__ b_ih,
                            const float* __restrict__ b_hh,
                            const float* __restrict__ W_hr,
                            const int*   __restrict__ nstep_p,
                            float* __restrict__ out, int T)
{
    __shared__ float s_wih[8 * HIDDEN];   // 128
    __shared__ float s_b[4 * HIDDEN];     // 64
    __shared__ float s_whr[2 * HIDDEN];   // 32

    int tid = threadIdx.x;
    if (tid < 8 * HIDDEN) s_wih[tid] = W_ih[tid];
    if (tid < 4 * HIDDEN) s_b[tid]   = b_ih[tid] + b_hh[tid];
    if (tid < 2 * HIDDEN) s_whr[tid] = W_hr[tid];
    __syncthreads();

    const int nstep = nstep_p ? *nstep_p : (T >> 1);
    const int b = blockIdx.y;
    const int t = blockIdx.x * blockDim.x + tid;
    if (t >= nstep) return;

    const float2 x = *reinterpret_cast<const float2*>(
        y_train + ((size_t)b * T + t) * 2);

    float y0 = 0.0f, y1 = 0.0f;
#pragma unroll
    for (int j = 0; j < HIDDEN; j++) {
        const int ri = j, rg = 32 + j, ro = 48 + j;
        float vi = fmaf(s_wih[2*ri],   x.x, fmaf(s_wih[2*ri+1], x.y, s_b[ri]));
        float vg = fmaf(s_wih[2*rg],   x.x, fmaf(s_wih[2*rg+1], x.y, s_b[rg]));
        float vo = fmaf(s_wih[2*ro],   x.x, fmaf(s_wih[2*ro+1], x.y, s_b[ro]));
        float c  = sigf(vi) * tanhf_(vg);
        float z  = sigf(vo) * tanhf_(c);
        y0 = fmaf(z, s_whr[j],          y0);
        y1 = fmaf(z, s_whr[HIDDEN + j], y1);
    }
    *reinterpret_cast<float2*>(out + ((size_t)b * T + t) * 2) =
        make_float2(y0, y1);
}

// ----------------------------------------------------------------------------
// Phase 2: sequential scan. lane j in a half-warp owns hidden unit j of one
// batch; gates in registers; projection h = z @ W_hr^T via shfl.xor butterfly.
// One warp per block (2 batches), grid = B/2 blocks -> one warp per SM.
// ----------------------------------------------------------------------------
__global__ void __launch_bounds__(32, 1)
lstm_phase2(const float* __restrict__ u_train,
            const float* __restrict__ y_train,
            const float* __restrict__ W_ih,
            const float* __restrict__ W_hh,
            const float* __restrict__ b_ih,
            const float* __restrict__ b_hh,
            const float* __restrict__ W_hr,
            const int*   __restrict__ nstep_p,
            float* __restrict__ out, int B, int T)
{
    const int lane  = threadIdx.x;                // 0..31
    int batch       = blockIdx.x * 2 + (lane >> 4);
    const int j     = lane & 15;                  // hidden index
    const bool active = (batch < B);
    if (!active) batch = B - 1;                   // keep shuffles converged

    // per-lane weights: rows {j, 16+j, 32+j, 48+j} = gates {i, f, g, o}
    float wih0[4], wih1[4], whh0[4], whh1[4], bs[4];
#pragma unroll
    for (int g = 0; g < 4; g++) {
        const int r = g * HIDDEN + j;
        wih0[g] = __ldg(W_ih + 2 * r);
        wih1[g] = __ldg(W_ih + 2 * r + 1);
        whh0[g] = __ldg(W_hh + 2 * r);
        whh1[g] = __ldg(W_hh + 2 * r + 1);
        bs[g]   = __ldg(b_ih + r) + __ldg(b_hh + r);
    }
    const float whr0 = __ldg(W_hr + j);
    const float whr1 = __ldg(W_hr + HIDDEN + j);

    const int nstep = nstep_p ? *nstep_p : (T >> 1);
    const size_t base = (size_t)batch * T;

    // ---- seed state from phase-1 step at t = nstep-1 (x from y_train) ------
    float c, h0, h1;
    {
        const float2 x = *reinterpret_cast<const float2*>(
            y_train + (base + nstep - 1) * 2);
        float vi = fmaf(wih0[0], x.x, fmaf(wih1[0], x.y, bs[0]));
        float vg = fmaf(wih0[2], x.x, fmaf(wih1[2], x.y, bs[2]));
        float vo = fmaf(wih0[3], x.x, fmaf(wih1[3], x.y, bs[3]));
        c = sigf(vi) * tanhf_(vg);
        float z = sigf(vo) * tanhf_(c);
        float p0 = z * whr0, p1 = z * whr1;
#pragma unroll
        for (int k = 8; k >= 1; k >>= 1) {
            p0 += __shfl_xor_sync(0xFFFFFFFFu, p0, k);
            p1 += __shfl_xor_sync(0xFFFFFFFFu, p1, k);
        }
        h0 = p0; h1 = p1;
    }

    // ---- main scan ----------------------------------------------------------
    const float2* __restrict__ xp =
        reinterpret_cast<const float2*>(u_train) + base + nstep;
    float2* __restrict__ op = reinterpret_cast<float2*>(out) + base + nstep;
    const int steps = T - nstep;

    float2 x = xp[0];
    for (int s = 0; s < steps; s++) {
        // prefetch a line ahead (clamped) so DRAM latency hides under compute
        {
            int pf = s + 16; if (pf > steps - 1) pf = steps - 1;
            asm volatile("prefetch.global.L1 [%0];" :: "l"(xp + pf));
        }
        int nx = s + 1; if (nx > steps - 1) nx = steps - 1;
        const float2 xn = xp[nx];

        // gates (input-part first, h-dependent FMAs last on the critical path)
        float v0 = fmaf(wih0[0], x.x, fmaf(wih1[0], x.y, bs[0]));
        float v1 = fmaf(wih0[1], x.x, fmaf(wih1[1], x.y, bs[1]));
        float v2 = fmaf(wih0[2], x.x, fmaf(wih1[2], x.y, bs[2]));
        float v3 = fmaf(wih0[3], x.x, fmaf(wih1[3], x.y, bs[3]));
        v0 = fmaf(whh0[0], h0, fmaf(whh1[0], h1, v0));
        v1 = fmaf(whh0[1], h0, fmaf(whh1[1], h1, v1));
        v2 = fmaf(whh0[2], h0, fmaf(whh1[2], h1, v2));
        v3 = fmaf(whh0[3], h0, fmaf(whh1[3], h1, v3));

        const float ig = sigf(v0) * tanhf_(v2);
        c = fmaf(sigf(v1), c, ig);
        const float z = sigf(v3) * tanhf_(c);

        float p0 = z * whr0, p1 = z * whr1;
#pragma unroll
        for (int k = 8; k >= 1; k >>= 1) {
            p0 += __shfl_xor_sync(0xFFFFFFFFu, p0, k);
            p1 += __shfl_xor_sync(0xFFFFFFFFu, p1, k);
        }
        h0 = p0; h1 = p1;

        if (j == 0 && active) op[s] = make_float2(h0, h1);
        x = xn;
    }
}

// ----------------------------------------------------------------------------
// launch
// ----------------------------------------------------------------------------
extern "C" void kernel_launch(void* const* d_in, const int* in_sizes, int n_in,
                              void* d_out, int out_size)
{
    const float* u_train = (const float*)d_in[0];
    const float* y_train = (const float*)d_in[1];
    const float* W_ih    = (const float*)d_in[2];
    const float* W_hh    = (const float*)d_in[3];
    const float* b_ih    = (const float*)d_in[4];
    const float* b_hh    = (const float*)d_in[5];
    const float* W_hr    = (const float*)d_in[6];
    const int*   nstep_p = (n_in >= 8) ? (const int*)d_in[7] : nullptr;

    const int B = BATCH;
    const int T = in_sizes[0] / (B * 2);   // u_train is (B, T, 2)
    float* out = (float*)d_out;

    // Phase 1: cover all t; threads with t >= nstep exit (nstep read on device)
    dim3 g1((T + 255) / 256, B);
    lstm_phase1<<<g1, 256>>>(y_train, W_ih, b_ih, b_hh, W_hr, nstep_p, out, T);

    // Phase 2: one warp per 2 batches, one warp per block
    lstm_phase2<<<(B + 1) / 2, 32>>>(u_train, y_train, W_ih, W_hh, b_ih, b_hh,
                                     W_hr, nstep_p, out, B, T);
}

// round 2
// speedup vs baseline: 1.1243x; 1.1243x over previous
#include <cuda_runtime.h>
#include <cuda_bf16.h>
#include <cstdint>

// ----------------------------------------------------------------------------
// OpenLSTM: HIDDEN=16, PROJ=2, INPUT=2. B=64, T=8192, nstep=4096.
// Fused kernel: first P2_BLOCKS blocks run the sequential scan (phase 2),
// remaining blocks run the fully-parallel prefix (phase 1) concurrently.
//
// Phase 2 layout: 8 lanes per batch, 2 hidden units per lane, 4 batches/warp.
//   - activations via MUFU.TANH (sigmoid = 0.5*tanh(0.5x)+0.5, with the 0.5
//     input scale folded into the i/f/o gate weights & biases)
//   - projection h = z @ W_hr^T via 3-level shfl.xor butterfly (8 lanes)
// ----------------------------------------------------------------------------

#define HIDDEN 16
#define BATCH  64
#define P2_BLOCKS (BATCH / 4)     // 16 blocks, 4 batches per warp
#define P1_TPB 256

// --- activations -------------------------------------------------------------
__device__ __forceinline__ float tanh_mufu(float x) {
    float y;
    asm("tanh.approx.f32 %0, %1;" : "=f"(y) : "f"(x));
    return y;
}
// precise versions for phase 1 (parallel, cheap; keeps half the output exact)
__device__ __forceinline__ float fast_ex2(float x) {
    float y; asm("ex2.approx.ftz.f32 %0, %1;" : "=f"(y) : "f"(x)); return y;
}
__device__ __forceinline__ float fast_rcp(float x) {
    float y; asm("rcp.approx.ftz.f32 %0, %1;" : "=f"(y) : "f"(x)); return y;
}
__device__ __forceinline__ float sig_precise(float x) {
    return fast_rcp(1.0f + fast_ex2(-1.4426950408889634f * x));
}
__device__ __forceinline__ float tanh_precise(float x) {
    return fmaf(2.0f, sig_precise(2.0f * x), -1.0f);
}

// ----------------------------------------------------------------------------
__global__ void __launch_bounds__(P1_TPB, 1)
lstm_fused(const float* __restrict__ u_train,
           const float* __restrict__ y_train,
           const float* __restrict__ W_ih,
           const float* __restrict__ W_hh,
           const float* __restrict__ b_ih,
           const float* __restrict__ b_hh,
           const float* __restrict__ W_hr,
           const int*   __restrict__ nstep_p,
           float* __restrict__ out, int T, int blocks_per_batch)
{
    const int nstep = nstep_p ? *nstep_p : (T >> 1);

    if (blockIdx.x >= P2_BLOCKS) {
        // ================= PHASE 1: parallel prefix ==========================
        __shared__ float s_wih[8 * HIDDEN];
        __shared__ float s_b[4 * HIDDEN];
        __shared__ float s_whr[2 * HIDDEN];
        const int tid = threadIdx.x;
        if (tid < 8 * HIDDEN) s_wih[tid] = W_ih[tid];
        if (tid < 4 * HIDDEN) s_b[tid]   = b_ih[tid] + b_hh[tid];
        if (tid < 2 * HIDDEN) s_whr[tid] = W_hr[tid];
        __syncthreads();

        const int pb = blockIdx.x - P2_BLOCKS;
        const int b  = pb / blocks_per_batch;
        const int t  = (pb % blocks_per_batch) * P1_TPB + tid;
        if (t >= nstep) return;

        const float2 x = *reinterpret_cast<const float2*>(
            y_train + ((size_t)b * T + t) * 2);

        float y0 = 0.0f, y1 = 0.0f;
#pragma unroll
        for (int j = 0; j < HIDDEN; j++) {
            const int ri = j, rg = 32 + j, ro = 48 + j;
            float vi = fmaf(s_wih[2*ri], x.x, fmaf(s_wih[2*ri+1], x.y, s_b[ri]));
            float vg = fmaf(s_wih[2*rg], x.x, fmaf(s_wih[2*rg+1], x.y, s_b[rg]));
            float vo = fmaf(s_wih[2*ro], x.x, fmaf(s_wih[2*ro+1], x.y, s_b[ro]));
            float c  = sig_precise(vi) * tanh_precise(vg);
            float z  = sig_precise(vo) * tanh_precise(c);
            y0 = fmaf(z, s_whr[j],          y0);
            y1 = fmaf(z, s_whr[HIDDEN + j], y1);
        }
        *reinterpret_cast<float2*>(out + ((size_t)b * T + t) * 2) =
            make_float2(y0, y1);
        return;
    }

    // ==================== PHASE 2: sequential scan ===========================
    if (threadIdx.x >= 32) return;
    const int lane  = threadIdx.x;
    const int sub   = lane >> 3;          // batch within warp (0..3)
    const int j8    = lane & 7;           // base hidden index (0..7)
    const int batch = blockIdx.x * 4 + sub;

    // per-lane weights for hidden units {j8, j8+8}, gates {i,f,g,o}.
    // i/f/o rows are pre-scaled by 0.5 (sigmoid via 0.5*tanh(0.5x)+0.5).
    float wih0[2][4], wih1[2][4], whh0[2][4], whh1[2][4], bs[2][4];
    float whr0[2], whr1[2];
#pragma unroll
    for (int h = 0; h < 2; h++) {
        const int j = j8 + 8 * h;
#pragma unroll
        for (int g = 0; g < 4; g++) {
            const int r = g * HIDDEN + j;
            const float sc = (g == 2) ? 1.0f : 0.5f;   // g-gate uses raw tanh
            wih0[h][g] = sc * __ldg(W_ih + 2 * r);
            wih1[h][g] = sc * __ldg(W_ih + 2 * r + 1);
            whh0[h][g] = sc * __ldg(W_hh + 2 * r);
            whh1[h][g] = sc * __ldg(W_hh + 2 * r + 1);
            bs[h][g]   = sc * (__ldg(b_ih + r) + __ldg(b_hh + r));
        }
        whr0[h] = __ldg(W_hr + j);
        whr1[h] = __ldg(W_hr + HIDDEN + j);
    }

    const size_t base = (size_t)batch * T;

    // ---- seed state from step t = nstep-1 (x from y_train, h_prev = 0) -----
    float c[2], h0, h1;
    {
        const float2 x = *reinterpret_cast<const float2*>(
            y_train + (base + nstep - 1) * 2);
        float p0 = 0.0f, p1 = 0.0f;
#pragma unroll
        for (int h = 0; h < 2; h++) {
            float vi = fmaf(wih0[h][0], x.x, fmaf(wih1[h][0], x.y, bs[h][0]));
            float vg = fmaf(wih0[h][2], x.x, fmaf(wih1[h][2], x.y, bs[h][2]));
            float vo = fmaf(wih0[h][3], x.x, fmaf(wih1[h][3], x.y, bs[h][3]));
            float si = fmaf(0.5f, tanh_mufu(vi), 0.5f);
            float so = fmaf(0.5f, tanh_mufu(vo), 0.5f);
            c[h] = si * tanh_mufu(vg);
            float z = so * tanh_mufu(c[h]);
            p0 = fmaf(z, whr0[h], p0);
            p1 = fmaf(z, whr1[h], p1);
        }
#pragma unroll
        for (int k = 4; k >= 1; k >>= 1) {
            p0 += __shfl_xor_sync(0xFFFFFFFFu, p0, k);
            p1 += __shfl_xor_sync(0xFFFFFFFFu, p1, k);
        }
        h0 = p0; h1 = p1;
    }

    // ---- main scan ----------------------------------------------------------
    const float2* __restrict__ xp =
        reinterpret_cast<const float2*>(u_train) + base + nstep;
    float2* __restrict__ op = reinterpret_cast<float2*>(out) + base + nstep;
    const int steps = T - nstep;

    float2 x = xp[0];
#pragma unroll 2
    for (int s = 0; s < steps; s++) {
        // prefetch one line ahead; next-x preload keeps LDG off the chain
        int pf = min(s + 16, steps - 1);
        asm volatile("prefetch.global.L1 [%0];" :: "l"(xp + pf));
        const float2 xn = xp[min(s + 1, steps - 1)];

        float p0, p1;
        {
            // x-part of gates is independent of h -> scheduled under the
            // previous butterfly's latency by the compiler.
            float v[2][4];
#pragma unroll
            for (int h = 0; h < 2; h++)
#pragma unroll
                for (int g = 0; g < 4; g++)
                    v[h][g] = fmaf(wih0[h][g], x.x,
                              fmaf(wih1[h][g], x.y, bs[h][g]));
#pragma unroll
            for (int h = 0; h < 2; h++)
#pragma unroll
                for (int g = 0; g < 4; g++)
                    v[h][g] = fmaf(whh0[h][g], h0,
                              fmaf(whh1[h][g], h1, v[h][g]));

            p0 = 0.0f; p1 = 0.0f;
#pragma unroll
            for (int h = 0; h < 2; h++) {
                const float si = fmaf(0.5f, tanh_mufu(v[h][0]), 0.5f);
                const float sf = fmaf(0.5f, tanh_mufu(v[h][1]), 0.5f);
                const float tg = tanh_mufu(v[h][2]);
                const float so = fmaf(0.5f, tanh_mufu(v[h][3]), 0.5f);
                c[h] = fmaf(sf, c[h], si * tg);
                const float z = so * tanh_mufu(c[h]);
                p0 = fmaf(z, whr0[h], p0);
                p1 = fmaf(z, whr1[h], p1);
            }
        }
#pragma unroll
        for (int k = 4; k >= 1; k >>= 1) {
            p0 += __shfl_xor_sync(0xFFFFFFFFu, p0, k);
            p1 += __shfl_xor_sync(0xFFFFFFFFu, p1, k);
        }
        h0 = p0; h1 = p1;

        if (j8 == 0) op[s] = make_float2(h0, h1);
        x = xn;
    }
}

// ----------------------------------------------------------------------------
extern "C" void kernel_launch(void* const* d_in, const int* in_sizes, int n_in,
                              void* d_out, int out_size)
{
    const float* u_train = (const float*)d_in[0];
    const float* y_train = (const float*)d_in[1];
    const float* W_ih    = (const float*)d_in[2];
    const float* W_hh    = (const float*)d_in[3];
    const float* b_ih    = (const float*)d_in[4];
    const float* b_hh    = (const float*)d_in[5];
    const float* W_hr    = (const float*)d_in[6];
    const int*   nstep_p = (n_in >= 8) ? (const int*)d_in[7] : nullptr;

    const int B = BATCH;
    const int T = in_sizes[0] / (B * 2);           // u_train is (B, T, 2)
    float* out = (float*)d_out;

    // phase-1 grid sized to cover all t < T (threads with t >= nstep exit)
    const int blocks_per_batch = (T + P1_TPB - 1) / P1_TPB;
    const int grid = P2_BLOCKS + B * blocks_per_batch;

    lstm_fused<<<grid, P1_TPB>>>(u_train, y_train, W_ih, W_hh, b_ih, b_hh,
                                 W_hr, nstep_p, out, T, blocks_per_batch);
}

// round 3
// speedup vs baseline: 1.3278x; 1.1809x over previous
#include <cuda_runtime.h>
#include <cuda_bf16.h>
#include <cstdint>

// ----------------------------------------------------------------------------
// OpenLSTM: HIDDEN=16, PROJ=2, INPUT=2. B=64, T=8192, nstep=4096.
// Fused kernel: first P2_BLOCKS blocks run the sequential scan (phase 2),
// remaining blocks run the fully-parallel prefix (phase 1) concurrently.
//
// Phase 2 layout (R3): 16 lanes per batch, ONE hidden unit per lane,
// 2 batches per warp -> 5 MUFU.TANH per lane per step (port = 40 cyc).
// Projection reduction via same-warp shared-memory gather:
//   STS.64 (p0,p1) -> 8x LDS.128 broadcast -> packed f32x2 add tree.
// ----------------------------------------------------------------------------

#define HIDDEN 16
#define BATCH  64
#define P2_BLOCKS (BATCH / 2)     // 32 scan blocks, 2 batches per warp
#define P1_TPB 256

// --- activations -------------------------------------------------------------
__device__ __forceinline__ float tanh_mufu(float x) {
    float y;
    asm("tanh.approx.f32 %0, %1;" : "=f"(y) : "f"(x));
    return y;
}
// precise versions for phase 1 (parallel, cheap; keeps half the output exact)
__device__ __forceinline__ float fast_ex2(float x) {
    float y; asm("ex2.approx.ftz.f32 %0, %1;" : "=f"(y) : "f"(x)); return y;
}
__device__ __forceinline__ float fast_rcp(float x) {
    float y; asm("rcp.approx.ftz.f32 %0, %1;" : "=f"(y) : "f"(x)); return y;
}
__device__ __forceinline__ float sig_precise(float x) {
    return fast_rcp(1.0f + fast_ex2(-1.4426950408889634f * x));
}
__device__ __forceinline__ float tanh_precise(float x) {
    return fmaf(2.0f, sig_precise(2.0f * x), -1.0f);
}

__device__ __forceinline__ unsigned long long addf32x2(unsigned long long a,
                                                       unsigned long long b) {
    unsigned long long r;
    asm("add.rn.f32x2 %0, %1, %2;" : "=l"(r) : "l"(a), "l"(b));
    return r;
}

// same-warp smem reduction: lane writes (p0,p1); all 16 lanes of the group
// read back all 16 pairs (128B, 8x LDS.128 broadcast) and tree-sum (f32x2).
__device__ __forceinline__ void reduce16(uint32_t addr_st, uint32_t addr_ld,
                                         float p0, float p1,
                                         float& h0, float& h1) {
    asm volatile("st.shared.v2.f32 [%0], {%1, %2};"
                 :: "r"(addr_st), "f"(p0), "f"(p1) : "memory");
    unsigned long long q[16];
#pragma unroll
    for (int k = 0; k < 8; k++) {
        asm volatile("ld.shared.v2.u64 {%0, %1}, [%2];"
                     : "=l"(q[2*k]), "=l"(q[2*k+1])
                     : "r"(addr_ld + 16u * k) : "memory");
    }
    unsigned long long t0 = addf32x2(q[0],  q[1]);
    unsigned long long t1 = addf32x2(q[2],  q[3]);
    unsigned long long t2 = addf32x2(q[4],  q[5]);
    unsigned long long t3 = addf32x2(q[6],  q[7]);
    unsigned long long t4 = addf32x2(q[8],  q[9]);
    unsigned long long t5 = addf32x2(q[10], q[11]);
    unsigned long long t6 = addf32x2(q[12], q[13]);
    unsigned long long t7 = addf32x2(q[14], q[15]);
    t0 = addf32x2(t0, t1);  t2 = addf32x2(t2, t3);
    t4 = addf32x2(t4, t5);  t6 = addf32x2(t6, t7);
    t0 = addf32x2(t0, t2);  t4 = addf32x2(t4, t6);
    t0 = addf32x2(t0, t4);
    asm("mov.b64 {%0, %1}, %2;" : "=f"(h0), "=f"(h1) : "l"(t0));
}

// ----------------------------------------------------------------------------
__global__ void __launch_bounds__(P1_TPB, 1)
lstm_fused(const float* __restrict__ u_train,
           const float* __restrict__ y_train,
           const float* __restrict__ W_ih,
           const float* __restrict__ W_hh,
           const float* __restrict__ b_ih,
           const float* __restrict__ b_hh,
           const float* __restrict__ W_hr,
           const int*   __restrict__ nstep_p,
           float* __restrict__ out, int T, int blocks_per_batch)
{
    const int nstep = nstep_p ? *nstep_p : (T >> 1);

    if (blockIdx.x >= P2_BLOCKS) {
        // ================= PHASE 1: parallel prefix ==========================
        __shared__ float s_wih[8 * HIDDEN];
        __shared__ float s_b[4 * HIDDEN];
        __shared__ float s_whr[2 * HIDDEN];
        const int tid = threadIdx.x;
        if (tid < 8 * HIDDEN) s_wih[tid] = W_ih[tid];
        if (tid < 4 * HIDDEN) s_b[tid]   = b_ih[tid] + b_hh[tid];
        if (tid < 2 * HIDDEN) s_whr[tid] = W_hr[tid];
        __syncthreads();

        const int pb = blockIdx.x - P2_BLOCKS;
        const int b  = pb / blocks_per_batch;
        const int t  = (pb % blocks_per_batch) * P1_TPB + tid;
        if (t >= nstep) return;

        const float2 x = *reinterpret_cast<const float2*>(
            y_train + ((size_t)b * T + t) * 2);

        float y0 = 0.0f, y1 = 0.0f;
#pragma unroll
        for (int j = 0; j < HIDDEN; j++) {
            const int ri = j, rg = 32 + j, ro = 48 + j;
            float vi = fmaf(s_wih[2*ri], x.x, fmaf(s_wih[2*ri+1], x.y, s_b[ri]));
            float vg = fmaf(s_wih[2*rg], x.x, fmaf(s_wih[2*rg+1], x.y, s_b[rg]));
            float vo = fmaf(s_wih[2*ro], x.x, fmaf(s_wih[2*ro+1], x.y, s_b[ro]));
            float c  = sig_precise(vi) * tanh_precise(vg);
            float z  = sig_precise(vo) * tanh_precise(c);
            y0 = fmaf(z, s_whr[j],          y0);
            y1 = fmaf(z, s_whr[HIDDEN + j], y1);
        }
        *reinterpret_cast<float2*>(out + ((size_t)b * T + t) * 2) =
            make_float2(y0, y1);
        return;
    }

    // ==================== PHASE 2: sequential scan ===========================
    if (threadIdx.x >= 32) return;
    __shared__ __align__(16) float2 s_red[2][HIDDEN];

    const int lane  = threadIdx.x;
    const int grp   = lane >> 4;          // batch within warp (0..1)
    const int j     = lane & 15;          // hidden unit index (0..15)
    const int batch = blockIdx.x * 2 + grp;

    uint32_t sbase;
    asm("{ .reg .u64 t; cvta.to.shared.u64 t, %1; cvt.u32.u64 %0, t; }"
        : "=r"(sbase) : "l"(&s_red[0][0]));
    const uint32_t addr_ld = sbase + (uint32_t)grp * (HIDDEN * 8);
    const uint32_t addr_st = addr_ld + (uint32_t)j * 8;

    // per-lane weights for hidden unit j, gates {i,f,g,o}.
    // i/f/o rows pre-scaled by 0.5 (sigmoid via 0.5*tanh(0.5x)+0.5).
    float wih0[4], wih1[4], whh0[4], whh1[4], bs[4];
#pragma unroll
    for (int g = 0; g < 4; g++) {
        const int r = g * HIDDEN + j;
        const float sc = (g == 2) ? 1.0f : 0.5f;   // g-gate uses raw tanh
        wih0[g] = sc * __ldg(W_ih + 2 * r);
        wih1[g] = sc * __ldg(W_ih + 2 * r + 1);
        whh0[g] = sc * __ldg(W_hh + 2 * r);
        whh1[g] = sc * __ldg(W_hh + 2 * r + 1);
        bs[g]   = sc * (__ldg(b_ih + r) + __ldg(b_hh + r));
    }
    const float whr0 = __ldg(W_hr + j);
    const float whr1 = __ldg(W_hr + HIDDEN + j);

    const size_t base = (size_t)batch * T;

    // ---- seed state from step t = nstep-1 (x from y_train, h_prev = 0) -----
    float c, halfc, h0, h1;
    {
        const float2 x = *reinterpret_cast<const float2*>(
            y_train + (base + nstep - 1) * 2);
        float vi = fmaf(wih0[0], x.x, fmaf(wih1[0], x.y, bs[0]));
        float vg = fmaf(wih0[2], x.x, fmaf(wih1[2], x.y, bs[2]));
        float vo = fmaf(wih0[3], x.x, fmaf(wih1[3], x.y, bs[3]));
        float si = fmaf(0.5f, tanh_mufu(vi), 0.5f);
        float so = fmaf(0.5f, tanh_mufu(vo), 0.5f);
        c = si * tanh_mufu(vg);
        halfc = 0.5f * c;
        float z = so * tanh_mufu(c);
        reduce16(addr_st, addr_ld, z * whr0, z * whr1, h0, h1);
    }

    // ---- main scan ----------------------------------------------------------
    const float2* __restrict__ xp =
        reinterpret_cast<const float2*>(u_train) + base + nstep;
    float2* __restrict__ op = reinterpret_cast<float2*>(out) + base + nstep;
    const int steps = T - nstep;

    float2 x = xp[0];
#pragma unroll 2
    for (int s = 0; s < steps; s++) {
        int pf = min(s + 16, steps - 1);
        asm volatile("prefetch.global.L1 [%0];" :: "l"(xp + pf));
        const float2 xn = xp[min(s + 1, steps - 1)];

        // x-part of gates: off the critical path (computed while the previous
        // step's reduction is in flight)
        float xb0 = fmaf(wih0[0], x.x, fmaf(wih1[0], x.y, bs[0]));
        float xb1 = fmaf(wih0[1], x.x, fmaf(wih1[1], x.y, bs[1]));
        float xb2 = fmaf(wih0[2], x.x, fmaf(wih1[2], x.y, bs[2]));
        float xb3 = fmaf(wih0[3], x.x, fmaf(wih1[3], x.y, bs[3]));

        // h-part (critical): 2 chained FMA per gate
        float v0 = fmaf(whh0[0], h0, fmaf(whh1[0], h1, xb0));
        float v1 = fmaf(whh0[1], h0, fmaf(whh1[1], h1, xb1));
        float v2 = fmaf(whh0[2], h0, fmaf(whh1[2], h1, xb2));
        float v3 = fmaf(whh0[3], h0, fmaf(whh1[3], h1, xb3));

        const float ti = tanh_mufu(v0);
        const float tg = tanh_mufu(v2);
        const float tf = tanh_mufu(v1);
        const float to = tanh_mufu(v3);

        const float si = fmaf(0.5f, ti, 0.5f);
        const float ig = si * tg;
        // c = sig(f)*c + ig  ==  tf*halfc + (halfc + ig)   (halfc off-chain)
        const float inner = halfc + ig;
        c = fmaf(tf, halfc, inner);
        halfc = 0.5f * c;

        const float tc = tanh_mufu(c);
        const float so = fmaf(0.5f, to, 0.5f);
        const float z  = so * tc;

        reduce16(addr_st, addr_ld, z * whr0, z * whr1, h0, h1);

        if (j == 0) op[s] = make_float2(h0, h1);
        x = xn;
    }
}

// ----------------------------------------------------------------------------
extern "C" void kernel_launch(void* const* d_in, const int* in_sizes, int n_in,
                              void* d_out, int out_size)
{
    const float* u_train = (const float*)d_in[0];
    const float* y_train = (const float*)d_in[1];
    const float* W_ih    = (const float*)d_in[2];
    const float* W_hh    = (const float*)d_in[3];
    const float* b_ih    = (const float*)d_in[4];
    const float* b_hh    = (const float*)d_in[5];
    const float* W_hr    = (const float*)d_in[6];
    const int*   nstep_p = (n_in >= 8) ? (const int*)d_in[7] : nullptr;

    const int B = BATCH;
    const int T = in_sizes[0] / (B * 2);           // u_train is (B, T, 2)
    float* out = (float*)d_out;

    // phase-1 grid sized to cover all t < T (threads with t >= nstep exit)
    const int blocks_per_batch = (T + P1_TPB - 1) / P1_TPB;
    const int grid = P2_BLOCKS + B * blocks_per_batch;

    lstm_fused<<<grid, P1_TPB>>>(u_train, y_train, W_ih, W_hh, b_ih, b_hh,
                                 W_hr, nstep_p, out, T, blocks_per_batch);
}

// round 5
// speedup vs baseline: 1.4645x; 1.1030x over previous
#include <cuda_runtime.h>
#include <cuda_bf16.h>
#include <cstdint>

// ----------------------------------------------------------------------------
// OpenLSTM: HIDDEN=16, PROJ=2, INPUT=2. B=64, T=8192, nstep=4096.
// Fused kernel: first P2_BLOCKS blocks run the sequential scan (phase 2),
// remaining blocks run the fully-parallel prefix (phase 1) concurrently.
//
// Phase 2 layout (R5): ONE batch per warp. Lanes 0-15 / 16-31 redundantly
// compute hidden unit j = lane&15; lower half weights projection by W_hr[0,:],
// upper half by W_hr[1,:]. The 16-lane reductions are done with
// REDUX.SUM.S32 on magic-number fixed-point (S = 2^19):
//   p_bits = bits(fma(z, whr*S, 2^23+2^22))          // 1 FMA quantize
//   h_bits = redux.sync.add.s32(sel(p_bits, BASE))   // 1 SEL + 1 REDUX
//   f      = as_float(h_bits - 0x1CC00000)           // = MAGIC + h*S, 1 IADD
// and f feeds the gate FMAs with whh/S-scaled weights (MAGIC folded in bias).
// ----------------------------------------------------------------------------

#define HIDDEN 16
#define BATCH  64
#define P2_BLOCKS (BATCH)         // 64 scan blocks, 1 batch per warp
#define P1_TPB 256

#define MAGICF  12582912.0f       // 2^23 + 2^22
#define BASEI   0x4B400000        // bit pattern of MAGICF
#define DEBIAS  0x1CC00000        // (31 * BASEI) mod 2^32
#define FIXS    524288.0f         // 2^19
#define INV_FIXS (1.0f / 524288.0f)

// --- activations -------------------------------------------------------------
__device__ __forceinline__ float tanh_mufu(float x) {
    float y;
    asm("tanh.approx.f32 %0, %1;" : "=f"(y) : "f"(x));
    return y;
}
// precise versions for phase 1 (parallel, cheap; keeps half the output exact)
__device__ __forceinline__ float fast_ex2(float x) {
    float y; asm("ex2.approx.ftz.f32 %0, %1;" : "=f"(y) : "f"(x)); return y;
}
__device__ __forceinline__ float fast_rcp(float x) {
    float y; asm("rcp.approx.ftz.f32 %0, %1;" : "=f"(y) : "f"(x)); return y;
}
__device__ __forceinline__ float sig_precise(float x) {
    return fast_rcp(1.0f + fast_ex2(-1.4426950408889634f * x));
}
__device__ __forceinline__ float tanh_precise(float x) {
    return fmaf(2.0f, sig_precise(2.0f * x), -1.0f);
}

__device__ __forceinline__ int redux_s32(int v) {
    int r;
    asm volatile("redux.sync.add.s32 %0, %1, 0xFFFFFFFF;" : "=r"(r) : "r"(v));
    return r;
}

// ----------------------------------------------------------------------------
__global__ void __launch_bounds__(P1_TPB, 1)
lstm_fused(const float* __restrict__ u_train,
           const float* __restrict__ y_train,
           const float* __restrict__ W_ih,
           const float* __restrict__ W_hh,
           const float* __restrict__ b_ih,
           const float* __restrict__ b_hh,
           const float* __restrict__ W_hr,
           const int*   __restrict__ nstep_p,
           float* __restrict__ out, int T, int blocks_per_batch)
{
    const int nstep = nstep_p ? *nstep_p : (T >> 1);

    if (blockIdx.x >= P2_BLOCKS) {
        // ================= PHASE 1: parallel prefix ==========================
        __shared__ float s_wih[8 * HIDDEN];
        __shared__ float s_b[4 * HIDDEN];
        __shared__ float s_whr[2 * HIDDEN];
        const int tid = threadIdx.x;
        if (tid < 8 * HIDDEN) s_wih[tid] = W_ih[tid];
        if (tid < 4 * HIDDEN) s_b[tid]   = b_ih[tid] + b_hh[tid];
        if (tid < 2 * HIDDEN) s_whr[tid] = W_hr[tid];
        __syncthreads();

        const int pb = blockIdx.x - P2_BLOCKS;
        const int b  = pb / blocks_per_batch;
        const int t  = (pb % blocks_per_batch) * P1_TPB + tid;
        if (t >= nstep) return;

        const float2 x = *reinterpret_cast<const float2*>(
            y_train + ((size_t)b * T + t) * 2);

        float y0 = 0.0f, y1 = 0.0f;
#pragma unroll
        for (int j = 0; j < HIDDEN; j++) {
            const int ri = j, rg = 32 + j, ro = 48 + j;
            float vi = fmaf(s_wih[2*ri], x.x, fmaf(s_wih[2*ri+1], x.y, s_b[ri]));
            float vg = fmaf(s_wih[2*rg], x.x, fmaf(s_wih[2*rg+1], x.y, s_b[rg]));
            float vo = fmaf(s_wih[2*ro], x.x, fmaf(s_wih[2*ro+1], x.y, s_b[ro]));
            float c  = sig_precise(vi) * tanh_precise(vg);
            float z  = sig_precise(vo) * tanh_precise(c);
            y0 = fmaf(z, s_whr[j],          y0);
            y1 = fmaf(z, s_whr[HIDDEN + j], y1);
        }
        *reinterpret_cast<float2*>(out + ((size_t)b * T + t) * 2) =
            make_float2(y0, y1);
        return;
    }

    // ==================== PHASE 2: sequential scan ===========================
    if (threadIdx.x >= 32) return;

    const int lane  = threadIdx.x;
    const bool low  = (lane < 16);        // low half -> h0, high half -> h1
    const int j     = lane & 15;          // hidden unit index (0..15)
    const int batch = blockIdx.x;

    // per-lane weights for hidden unit j, gates {i,f,g,o}.
    // i/f/o rows pre-scaled by 0.5 (sigmoid via 0.5*tanh(0.5x)+0.5).
    // h-weights additionally divided by FIXS (h arrives as MAGIC + h*FIXS,
    // with the MAGIC offset folded into the bias).
    float wih0[4], wih1[4], whh0s[4], whh1s[4], bs[4];
#pragma unroll
    for (int g = 0; g < 4; g++) {
        const int r = g * HIDDEN + j;
        const float sc = (g == 2) ? 1.0f : 0.5f;   // g-gate uses raw tanh
        wih0[g]  = sc * __ldg(W_ih + 2 * r);
        wih1[g]  = sc * __ldg(W_ih + 2 * r + 1);
        whh0s[g] = sc * __ldg(W_hh + 2 * r)     * INV_FIXS;
        whh1s[g] = sc * __ldg(W_hh + 2 * r + 1) * INV_FIXS;
        bs[g]    = sc * (__ldg(b_ih + r) + __ldg(b_hh + r))
                   - (whh0s[g] + whh1s[g]) * MAGICF;
    }
    // projection weight for this lane's half, pre-scaled for quantization
    const float whr_s = __ldg(W_hr + (low ? 0 : HIDDEN) + j) * FIXS;

    const size_t base = (size_t)batch * T;

    // ---- seed state from step t = nstep-1 (x from y_train, h_prev = 0) -----
    float c, halfc, f0, f1;   // f0/f1 = MAGIC + h0*S / MAGIC + h1*S
    {
        const float2 x = *reinterpret_cast<const float2*>(
            y_train + (base + nstep - 1) * 2);
        // note: bias here must NOT include the -MAGIC fold (h_prev = 0), so
        // rebuild the raw bias for the seed step.
        float rb[4];
#pragma unroll
        for (int g = 0; g < 4; g++)
            rb[g] = bs[g] + (whh0s[g] + whh1s[g]) * MAGICF;
        float vi = fmaf(wih0[0], x.x, fmaf(wih1[0], x.y, rb[0]));
        float vg = fmaf(wih0[2], x.x, fmaf(wih1[2], x.y, rb[2]));
        float vo = fmaf(wih0[3], x.x, fmaf(wih1[3], x.y, rb[3]));
        float si = fmaf(0.5f, tanh_mufu(vi), 0.5f);
        float so = fmaf(0.5f, tanh_mufu(vo), 0.5f);
        c = si * tanh_mufu(vg);
        halfc = 0.5f * c;
        float z = so * tanh_mufu(c);
        const int pb = __float_as_int(fmaf(z, whr_s, MAGICF));
        const int q0 = low ? pb : BASEI;
        const int q1 = low ? BASEI : pb;
        f0 = __int_as_float(redux_s32(q0) - DEBIAS);
        f1 = __int_as_float(redux_s32(q1) - DEBIAS);
    }

    // ---- main scan ----------------------------------------------------------
    const float2* __restrict__ xp =
        reinterpret_cast<const float2*>(u_train) + base + nstep;
    float2* __restrict__ op = reinterpret_cast<float2*>(out) + base + nstep;
    const int steps = T - nstep;

    float2 x = xp[0];
#pragma unroll 2
    for (int s = 0; s < steps; s++) {
        int pf = min(s + 16, steps - 1);
        asm volatile("prefetch.global.L1 [%0];" :: "l"(xp + pf));
        const float2 xn = xp[min(s + 1, steps - 1)];

        // x-part of gates: off the critical path (scheduled under the
        // previous step's redux latency). bias already folds -MAGIC terms.
        float xb0 = fmaf(wih0[0], x.x, fmaf(wih1[0], x.y, bs[0]));
        float xb1 = fmaf(wih0[1], x.x, fmaf(wih1[1], x.y, bs[1]));
        float xb2 = fmaf(wih0[2], x.x, fmaf(wih1[2], x.y, bs[2]));
        float xb3 = fmaf(wih0[3], x.x, fmaf(wih1[3], x.y, bs[3]));

        // h-part (critical): 2 chained FMA per gate, consuming biased h
        float v0 = fmaf(whh0s[0], f0, fmaf(whh1s[0], f1, xb0));
        float v1 = fmaf(whh0s[1], f0, fmaf(whh1s[1], f1, xb1));
        float v2 = fmaf(whh0s[2], f0, fmaf(whh1s[2], f1, xb2));
        float v3 = fmaf(whh0s[3], f0, fmaf(whh1s[3], f1, xb3));

        // g first (earliest consumer), then i, f, o
        const float tg = tanh_mufu(v2);
        const float ti = tanh_mufu(v0);
        const float tf = tanh_mufu(v1);
        const float to = tanh_mufu(v3);

        const float si = fmaf(0.5f, ti, 0.5f);
        const float ig = si * tg;
        // c = sig(f)*c + ig == tf*halfc + (halfc + ig)    (halfc off-chain)
        const float inner = halfc + ig;
        c = fmaf(tf, halfc, inner);
        halfc = 0.5f * c;

        const float tc = tanh_mufu(c);
        const float so = fmaf(0.5f, to, 0.5f);
        const float z  = so * tc;

        // fixed-point quantize + warp reduce
        const int pb = __float_as_int(fmaf(z, whr_s, MAGICF));
        const int q0 = low ? pb : BASEI;
        const int q1 = low ? BASEI : pb;
        f0 = __int_as_float(redux_s32(q0) - DEBIAS);
        f1 = __int_as_float(redux_s32(q1) - DEBIAS);

        if (lane == 0)
            op[s] = make_float2((f0 - MAGICF) * INV_FIXS,
                                (f1 - MAGICF) * INV_FIXS);
        x = xn;
    }
}

// ----------------------------------------------------------------------------
extern "C" void kernel_launch(void* const* d_in, const int* in_sizes, int n_in,
                              void* d_out, int out_size)
{
    const float* u_train = (const float*)d_in[0];
    const float* y_train = (const float*)d_in[1];
    const float* W_ih    = (const float*)d_in[2];
    const float* W_hh    = (const float*)d_in[3];
    const float* b_ih    = (const float*)d_in[4];
    const float* b_hh    = (const float*)d_in[5];
    const float* W_hr    = (const float*)d_in[6];
    const int*   nstep_p = (n_in >= 8) ? (const int*)d_in[7] : nullptr;

    const int B = BATCH;
    const int T = in_sizes[0] / (B * 2);           // u_train is (B, T, 2)
    float* out = (float*)d_out;

    // phase-1 grid sized to cover all t < T (threads with t >= nstep exit)
    const int blocks_per_batch = (T + P1_TPB - 1) / P1_TPB;
    const int grid = P2_BLOCKS + B * blocks_per_batch;

    lstm_fused<<<grid, P1_TPB>>>(u_train, y_train, W_ih, W_hh, b_ih, b_hh,
                                 W_hr, nstep_p, out, T, blocks_per_batch);
}

// round 6
// speedup vs baseline: 1.5894x; 1.0853x over previous
#include <cuda_runtime.h>
#include <cuda_bf16.h>
#include <cstdint>

// ----------------------------------------------------------------------------
// OpenLSTM: HIDDEN=16, PROJ=2, INPUT=2. B=64, T=8192, nstep=4096.
// Fused kernel: first P2_BLOCKS blocks run the sequential scan (phase 2),
// remaining blocks run the fully-parallel prefix (phase 1) concurrently.
//
// Phase 2 (R6): one batch per warp; lanes 0-15 / 16-31 redundantly compute
// hidden unit j = lane&15. Projection sums via REDUX.SUM.S32 on magic-number
// fixed point (S = 2^19):
//   p_bits = bits(fma(so*whr_s, tanh(c), MAGIC))   // whr_s = 0 on other half
//   h_bits = redux.sync.add.s32(p_bits)
//   f      = as_float(h_bits - DEBIAS)             // = MAGIC + h*S
// f feeds gate FMAs with whh/S-scaled weights (MAGIC folded into bias).
// Inner loop: 16-step chunks, fully unrolled, 1 prefetch per chunk.
// ----------------------------------------------------------------------------

#define HIDDEN 16
#define BATCH  64
#define P2_BLOCKS (BATCH)         // 64 scan blocks, 1 batch per warp
#define P1_TPB 256

#define MAGICF  12582912.0f       // 2^23 + 2^22
#define BASEI   0x4B400000        // bit pattern of MAGICF
#define DEBIAS  0x1CC00000        // (31 * BASEI) mod 2^32
#define FIXS    524288.0f         // 2^19
#define INV_FIXS (1.0f / 524288.0f)

// --- activations -------------------------------------------------------------
__device__ __forceinline__ float tanh_mufu(float x) {
    float y;
    asm("tanh.approx.f32 %0, %1;" : "=f"(y) : "f"(x));
    return y;
}
__device__ __forceinline__ float fast_ex2(float x) {
    float y; asm("ex2.approx.ftz.f32 %0, %1;" : "=f"(y) : "f"(x)); return y;
}
__device__ __forceinline__ float fast_rcp(float x) {
    float y; asm("rcp.approx.ftz.f32 %0, %1;" : "=f"(y) : "f"(x)); return y;
}
__device__ __forceinline__ float sig_precise(float x) {
    return fast_rcp(1.0f + fast_ex2(-1.4426950408889634f * x));
}
__device__ __forceinline__ float tanh_precise(float x) {
    return fmaf(2.0f, sig_precise(2.0f * x), -1.0f);
}

__device__ __forceinline__ int redux_s32(int v) {
    int r;
    asm volatile("redux.sync.add.s32 %0, %1, 0xFFFFFFFF;" : "=r"(r) : "r"(v));
    return r;
}

// ----------------------------------------------------------------------------
__global__ void __launch_bounds__(P1_TPB, 1)
lstm_fused(const float* __restrict__ u_train,
           const float* __restrict__ y_train,
           const float* __restrict__ W_ih,
           const float* __restrict__ W_hh,
           const float* __restrict__ b_ih,
           const float* __restrict__ b_hh,
           const float* __restrict__ W_hr,
           const int*   __restrict__ nstep_p,
           float* __restrict__ out, int T, int blocks_per_batch)
{
    const int nstep = nstep_p ? *nstep_p : (T >> 1);

    if (blockIdx.x >= P2_BLOCKS) {
        // ================= PHASE 1: parallel prefix ==========================
        __shared__ float s_wih[8 * HIDDEN];
        __shared__ float s_b[4 * HIDDEN];
        __shared__ float s_whr[2 * HIDDEN];
        const int tid = threadIdx.x;
        if (tid < 8 * HIDDEN) s_wih[tid] = W_ih[tid];
        if (tid < 4 * HIDDEN) s_b[tid]   = b_ih[tid] + b_hh[tid];
        if (tid < 2 * HIDDEN) s_whr[tid] = W_hr[tid];
        __syncthreads();

        const int pb = blockIdx.x - P2_BLOCKS;
        const int b  = pb / blocks_per_batch;
        const int t  = (pb % blocks_per_batch) * P1_TPB + tid;
        if (t >= nstep) return;

        const float2 x = *reinterpret_cast<const float2*>(
            y_train + ((size_t)b * T + t) * 2);

        float y0 = 0.0f, y1 = 0.0f;
#pragma unroll
        for (int j = 0; j < HIDDEN; j++) {
            const int ri = j, rg = 32 + j, ro = 48 + j;
            float vi = fmaf(s_wih[2*ri], x.x, fmaf(s_wih[2*ri+1], x.y, s_b[ri]));
            float vg = fmaf(s_wih[2*rg], x.x, fmaf(s_wih[2*rg+1], x.y, s_b[rg]));
            float vo = fmaf(s_wih[2*ro], x.x, fmaf(s_wih[2*ro+1], x.y, s_b[ro]));
            float c  = sig_precise(vi) * tanh_precise(vg);
            float z  = sig_precise(vo) * tanh_precise(c);
            y0 = fmaf(z, s_whr[j],          y0);
            y1 = fmaf(z, s_whr[HIDDEN + j], y1);
        }
        *reinterpret_cast<float2*>(out + ((size_t)b * T + t) * 2) =
            make_float2(y0, y1);
        return;
    }

    // ==================== PHASE 2: sequential scan ===========================
    if (threadIdx.x >= 32) return;

    const int lane  = threadIdx.x;
    const bool low  = (lane < 16);        // low half -> h0, high half -> h1
    const int j     = lane & 15;          // hidden unit index (0..15)
    const int batch = blockIdx.x;

    float wih0[4], wih1[4], whh0s[4], whh1s[4], bs[4];
#pragma unroll
    for (int g = 0; g < 4; g++) {
        const int r = g * HIDDEN + j;
        const float sc = (g == 2) ? 1.0f : 0.5f;   // g-gate uses raw tanh
        wih0[g]  = sc * __ldg(W_ih + 2 * r);
        wih1[g]  = sc * __ldg(W_ih + 2 * r + 1);
        whh0s[g] = sc * __ldg(W_hh + 2 * r)     * INV_FIXS;
        whh1s[g] = sc * __ldg(W_hh + 2 * r + 1) * INV_FIXS;
        bs[g]    = sc * (__ldg(b_ih + r) + __ldg(b_hh + r))
                   - (whh0s[g] + whh1s[g]) * MAGICF;
    }
    // projection weights, pre-scaled; zero on the non-contributing half so the
    // quantize FMA yields exactly BASEI bits there.
    const float whr_s0 = low ? __ldg(W_hr + j) * FIXS : 0.0f;
    const float whr_s1 = low ? 0.0f : __ldg(W_hr + HIDDEN + j) * FIXS;

    const size_t base = (size_t)batch * T;

    float c, halfc, f0, f1;   // f = MAGIC + h*S
    {
        const float2 x = *reinterpret_cast<const float2*>(
            y_train + (base + nstep - 1) * 2);
        float rb[4];
#pragma unroll
        for (int g = 0; g < 4; g++)
            rb[g] = bs[g] + (whh0s[g] + whh1s[g]) * MAGICF;
        float vi = fmaf(wih0[0], x.x, fmaf(wih1[0], x.y, rb[0]));
        float vg = fmaf(wih0[2], x.x, fmaf(wih1[2], x.y, rb[2]));
        float vo = fmaf(wih0[3], x.x, fmaf(wih1[3], x.y, rb[3]));
        float si = fmaf(0.5f, tanh_mufu(vi), 0.5f);
        float so = fmaf(0.5f, tanh_mufu(vo), 0.5f);
        c = si * tanh_mufu(vg);
        halfc = 0.5f * c;
        const float tc = tanh_mufu(c);
        const int q0 = __float_as_int(fmaf(so * whr_s0, tc, MAGICF));
        const int q1 = __float_as_int(fmaf(so * whr_s1, tc, MAGICF));
        f0 = __int_as_float(redux_s32(q0) - DEBIAS);
        f1 = __int_as_float(redux_s32(q1) - DEBIAS);
    }

    const float2* __restrict__ xp =
        reinterpret_cast<const float2*>(u_train) + base + nstep;
    float2* __restrict__ op = reinterpret_cast<float2*>(out) + base + nstep;
    const int steps = T - nstep;

    float2 x = (steps > 0) ? xp[0] : make_float2(0.f, 0.f);

    // one LSTM step; xn must be a VALID preloaded next-x
#define LSTM_STEP(S_IDX, XN)                                                   \
    {                                                                          \
        const float2 xn_ = (XN);                                               \
        float xb0 = fmaf(wih0[0], x.x, fmaf(wih1[0], x.y, bs[0]));             \
        float xb1 = fmaf(wih0[1], x.x, fmaf(wih1[1], x.y, bs[1]));             \
        float xb2 = fmaf(wih0[2], x.x, fmaf(wih1[2], x.y, bs[2]));             \
        float xb3 = fmaf(wih0[3], x.x, fmaf(wih1[3], x.y, bs[3]));             \
        float v0 = fmaf(whh0s[0], f0, fmaf(whh1s[0], f1, xb0));                \
        float v1 = fmaf(whh0s[1], f0, fmaf(whh1s[1], f1, xb1));                \
        float v2 = fmaf(whh0s[2], f0, fmaf(whh1s[2], f1, xb2));                \
        float v3 = fmaf(whh0s[3], f0, fmaf(whh1s[3], f1, xb3));                \
        const float tg = tanh_mufu(v2);                                        \
        const float ti = tanh_mufu(v0);                                        \
        const float tf = tanh_mufu(v1);                                        \
        const float to = tanh_mufu(v3);                                        \
        const float si = fmaf(0.5f, ti, 0.5f);                                 \
        const float ig = si * tg;                                              \
        const float inner = halfc + ig;                                        \
        c = fmaf(tf, halfc, inner);                                            \
        halfc = 0.5f * c;                                                      \
        const float so  = fmaf(0.5f, to, 0.5f);                                \
        const float so0 = so * whr_s0;                                         \
        const float so1 = so * whr_s1;                                         \
        const float tc = tanh_mufu(c);                                         \
        const int q0 = __float_as_int(fmaf(so0, tc, MAGICF));                  \
        const int q1 = __float_as_int(fmaf(so1, tc, MAGICF));                  \
        f0 = __int_as_float(redux_s32(q0) - DEBIAS);                           \
        f1 = __int_as_float(redux_s32(q1) - DEBIAS);                           \
        if (lane == 0)                                                         \
            op[S_IDX] = make_float2((f0 - MAGICF) * INV_FIXS,                  \
                                    (f1 - MAGICF) * INV_FIXS);                 \
        x = xn_;                                                               \
    }

    int s = 0;
    // full 16-step chunks: all xn loads (s+1 .. s+16) stay in-bounds
    for (; s + 17 <= steps; s += 16) {
        const float2* pfa = xp + min(s + 48, steps - 1);
        asm volatile("prefetch.global.L1 [%0];" :: "l"(pfa));
#pragma unroll
        for (int k = 0; k < 16; k++) {
            LSTM_STEP(s + k, xp[s + k + 1]);
        }
    }
    // tail
    for (; s < steps; s++) {
        LSTM_STEP(s, xp[min(s + 1, steps - 1)]);
    }
#undef LSTM_STEP
}

// ----------------------------------------------------------------------------
extern "C" void kernel_launch(void* const* d_in, const int* in_sizes, int n_in,
                              void* d_out, int out_size)
{
    const float* u_train = (const float*)d_in[0];
    const float* y_train = (const float*)d_in[1];
    const float* W_ih    = (const float*)d_in[2];
    const float* W_hh    = (const float*)d_in[3];
    const float* b_ih    = (const float*)d_in[4];
    const float* b_hh    = (const float*)d_in[5];
    const float* W_hr    = (const float*)d_in[6];
    const int*   nstep_p = (n_in >= 8) ? (const int*)d_in[7] : nullptr;

    const int B = BATCH;
    const int T = in_sizes[0] / (B * 2);           // u_train is (B, T, 2)
    float* out = (float*)d_out;

    const int blocks_per_batch = (T + P1_TPB - 1) / P1_TPB;
    const int grid = P2_BLOCKS + B * blocks_per_batch;

    lstm_fused<<<grid, P1_TPB>>>(u_train, y_train, W_ih, W_hh, b_ih, b_hh,
                                 W_hr, nstep_p, out, T, blocks_per_batch);
}